// round 1
// baseline (speedup 1.0000x reference)
#include <cuda_runtime.h>

#define SEQ  4096
#define EMBD 200
#define HID  256
#define G3   768            // 3*HID gate rows
#define CL   8              // cluster size (CTAs per direction)
#define SLICE 32            // HID / CL  h-outputs per CTA
#define HPAD  36            // padded chunk stride (32 + 4) -> conflict-free banks

// output layout: [embeddings 4096*200][hiddens 4096*512][h1 256][h2 256]
#define OFF_HID (SEQ * EMBD)               // 819200
#define OFF_H1  (OFF_HID + SEQ * 2 * HID)  // 2916352
#define OFF_H2  (OFF_H1 + HID)             // 2916608

// scratch: precomputed gi = W_ih @ x_t + b_ih for both directions
__device__ float g_gi[2ull * SEQ * G3];

// ---------------------------------------------------------------------------
// Kernel 1: embedding gather -> output section 0
// ---------------------------------------------------------------------------
__global__ void embed_kernel(const int* __restrict__ utt,
                             const float* __restrict__ emb,
                             float* __restrict__ out)
{
    int idx = blockIdx.x * blockDim.x + threadIdx.x;
    if (idx >= SEQ * EMBD) return;
    int t = idx / EMBD;
    int e = idx - t * EMBD;
    out[idx] = emb[(size_t)utt[t] * EMBD + e];
}

// ---------------------------------------------------------------------------
// Kernel 2: gi[d][t][r] = b_ih[r] + sum_k w_ih[r][k] * emb[utt[t]][k]
// tiled fp32 GEMM, 64x64 tiles, k-chunks of 8 (EMBD = 200 = 25*8)
// grid: (768/64, 4096/64, 2) = (12, 64, 2), 256 threads
// ---------------------------------------------------------------------------
__global__ void gi_gemm_kernel(const int* __restrict__ utt,
                               const float* __restrict__ emb,
                               const float* __restrict__ wih1,
                               const float* __restrict__ bih1,
                               const float* __restrict__ wih2,
                               const float* __restrict__ bih2)
{
    __shared__ float As[8][64];
    __shared__ float Bs[8][68];   // +4 pad
    __shared__ int   ut[64];

    const int dir = blockIdx.z;
    const float* __restrict__ wih = dir ? wih2 : wih1;
    const float* __restrict__ bih = dir ? bih2 : bih1;
    float* __restrict__ outp = g_gi + (size_t)dir * SEQ * G3;

    const int r0 = blockIdx.x * 64;
    const int t0 = blockIdx.y * 64;
    const int tid = threadIdx.x;

    if (tid < 64) ut[tid] = utt[t0 + tid];
    __syncthreads();

    const int tx = tid & 15;     // r micro-tile
    const int ty = tid >> 4;     // t micro-tile
    float c[4][4] = {};

    for (int k0 = 0; k0 < EMBD; k0 += 8) {
#pragma unroll
        for (int l = 0; l < 2; l++) {
            int e  = tid + l * 256;
            int kk = e >> 6;
            int o  = e & 63;
            As[kk][o] = emb[(size_t)ut[o] * EMBD + k0 + kk];
            Bs[kk][o] = wih[(size_t)(r0 + o) * EMBD + k0 + kk];
        }
        __syncthreads();
#pragma unroll
        for (int k = 0; k < 8; k++) {
            float4 a = *(const float4*)&As[k][ty * 4];
            float4 b = *(const float4*)&Bs[k][tx * 4];
            c[0][0] = fmaf(a.x, b.x, c[0][0]); c[0][1] = fmaf(a.x, b.y, c[0][1]);
            c[0][2] = fmaf(a.x, b.z, c[0][2]); c[0][3] = fmaf(a.x, b.w, c[0][3]);
            c[1][0] = fmaf(a.y, b.x, c[1][0]); c[1][1] = fmaf(a.y, b.y, c[1][1]);
            c[1][2] = fmaf(a.y, b.z, c[1][2]); c[1][3] = fmaf(a.y, b.w, c[1][3]);
            c[2][0] = fmaf(a.z, b.x, c[2][0]); c[2][1] = fmaf(a.z, b.y, c[2][1]);
            c[2][2] = fmaf(a.z, b.z, c[2][2]); c[2][3] = fmaf(a.z, b.w, c[2][3]);
            c[3][0] = fmaf(a.w, b.x, c[3][0]); c[3][1] = fmaf(a.w, b.y, c[3][1]);
            c[3][2] = fmaf(a.w, b.z, c[3][2]); c[3][3] = fmaf(a.w, b.w, c[3][3]);
        }
        __syncthreads();
    }

    float4 bb = *(const float4*)&bih[r0 + tx * 4];
#pragma unroll
    for (int i = 0; i < 4; i++) {
        int row = t0 + ty * 4 + i;
        float4 v;
        v.x = c[i][0] + bb.x;
        v.y = c[i][1] + bb.y;
        v.z = c[i][2] + bb.z;
        v.w = c[i][3] + bb.w;
        *(float4*)&outp[(size_t)row * G3 + r0 + tx * 4] = v;
    }
}

// ---------------------------------------------------------------------------
// Kernel 3: the sequential bi-GRU recurrence.
// grid = 16 CTAs: blocks 0-7 = forward cluster, 8-15 = backward cluster.
// Each CTA (256 threads) owns SLICE=32 h-outputs: all 3 gate rows, weights in
// registers (96 fp32/thread). h broadcast via DSMEM + flag sync per step.
// ---------------------------------------------------------------------------
__global__ void __launch_bounds__(256, 1) __cluster_dims__(CL, 1, 1)
gru_kernel(const float* __restrict__ whh1, const float* __restrict__ bhh1,
           const float* __restrict__ whh2, const float* __restrict__ bhh2,
           const float* __restrict__ h01,  const float* __restrict__ h02,
           float* __restrict__ out)
{
    __shared__ float    hbuf[2][CL * HPAD];   // double-buffered h (padded chunks)
    __shared__ unsigned flags[CL];            // per-source-rank step counters

    const int rank = blockIdx.x & (CL - 1);
    const int dir  = blockIdx.x >> 3;
    const float* __restrict__ whh = dir ? whh2 : whh1;
    const float* __restrict__ bhh = dir ? bhh2 : bhh1;
    const float* __restrict__ h0  = dir ? h02  : h01;
    const float* __restrict__ gi  = g_gi + (size_t)dir * SEQ * G3;
    float* __restrict__ ohid  = out + OFF_HID;
    float* __restrict__ olast = out + (dir ? OFF_H2 : OFF_H1);

    const int tid   = threadIdx.x;
    const int group = tid >> 3;        // 0..31 -> which h-output of my slice
    const int sub   = tid & 7;         // 0..7  -> which 32-wide k-chunk
    const int j     = rank * SLICE + group;   // global h index 0..255
    const int kb    = sub * 32;

    // ---- load my 96 weights into registers (rows j, 256+j, 512+j; cols kb..kb+31)
    float wr[32], wz[32], wn[32];
    {
        const float4* pr = (const float4*)(whh + (size_t)(          j) * HID + kb);
        const float4* pz = (const float4*)(whh + (size_t)(HID     + j) * HID + kb);
        const float4* pn = (const float4*)(whh + (size_t)(2 * HID + j) * HID + kb);
#pragma unroll
        for (int i = 0; i < 8; i++) {
            float4 a = pr[i]; wr[4*i]=a.x; wr[4*i+1]=a.y; wr[4*i+2]=a.z; wr[4*i+3]=a.w;
            float4 b = pz[i]; wz[4*i]=b.x; wz[4*i+1]=b.y; wz[4*i+2]=b.z; wz[4*i+3]=b.w;
            float4 d = pn[i]; wn[4*i]=d.x; wn[4*i+1]=d.y; wn[4*i+2]=d.z; wn[4*i+3]=d.w;
        }
    }

    // ---- init h buffer 0 (padded layout: element k at chunk k/32, offset k%32)
    if (tid < HID) hbuf[0][(tid >> 5) * HPAD + (tid & 31)] = h0[tid];
    if (tid < CL)  flags[tid] = 0;

    float bhr = 0.f, bhz = 0.f, bhn = 0.f;
    float gr = 0.f, gz = 0.f, gn = 0.f;
    if (sub == 0) {
        bhr = bhh[j]; bhz = bhh[HID + j]; bhn = bhh[2 * HID + j];
        int tr = dir ? (SEQ - 1) : 0;
        const float* gp = gi + (size_t)tr * G3;
        gr = gp[j]; gz = gp[HID + j]; gn = gp[2 * HID + j];
    }
    __syncthreads();
    // all CTAs of the cluster must have flags=0 before anyone can push
    asm volatile("barrier.cluster.arrive.aligned;" ::: "memory");
    asm volatile("barrier.cluster.wait.aligned;"   ::: "memory");

    for (int t = 0; t < SEQ; t++) {
        const int p  = t & 1;
        const int p2 = p ^ 1;

        // prefetch next step's gi early (latency hidden under this step)
        float ngr = 0.f, ngz = 0.f, ngn = 0.f;
        if (sub == 0 && t < SEQ - 1) {
            int tr = dir ? (SEQ - 2 - t) : (t + 1);
            const float* gp = gi + (size_t)tr * G3;
            ngr = gp[j]; ngz = gp[HID + j]; ngn = gp[2 * HID + j];
        }

        // ---- partial dots over my k-chunk (weights in regs, h from smem)
        float ar = 0.f, az = 0.f, an = 0.f;
        const float4* hs = (const float4*)&hbuf[p][sub * HPAD];
#pragma unroll
        for (int i = 0; i < 8; i++) {
            float4 h4 = hs[i];
            ar = fmaf(wr[4*i  ], h4.x, ar); az = fmaf(wz[4*i  ], h4.x, az); an = fmaf(wn[4*i  ], h4.x, an);
            ar = fmaf(wr[4*i+1], h4.y, ar); az = fmaf(wz[4*i+1], h4.y, az); an = fmaf(wn[4*i+1], h4.y, an);
            ar = fmaf(wr[4*i+2], h4.z, ar); az = fmaf(wz[4*i+2], h4.z, az); an = fmaf(wn[4*i+2], h4.z, an);
            ar = fmaf(wr[4*i+3], h4.w, ar); az = fmaf(wz[4*i+3], h4.w, az); an = fmaf(wn[4*i+3], h4.w, an);
        }
        // ---- reduce across the 8 subs of this group (within-warp, width 8)
#pragma unroll
        for (int off = 4; off; off >>= 1) {
            ar += __shfl_xor_sync(0xffffffffu, ar, off, 8);
            az += __shfl_xor_sync(0xffffffffu, az, off, 8);
            an += __shfl_xor_sync(0xffffffffu, an, off, 8);
        }

        if (sub == 0) {
            float xr = gr + bhr + ar;
            float xz = gz + bhz + az;
            float r  = __fdividef(1.f, 1.f + __expf(-xr));
            float z  = __fdividef(1.f, 1.f + __expf(-xz));
            float xn = gn + r * (an + bhn);
            float e2 = __expf(-2.f * xn);
            float n  = __fdividef(1.f - e2, 1.f + e2);   // tanh(xn)
            float hp = hbuf[p][rank * HPAD + group];      // h_prev[j]
            float hnew = n + z * (hp - n);                // (1-z)n + z h

            hbuf[p2][rank * HPAD + group] = hnew;         // local slice -> next buffer
            int tr = dir ? (SEQ - 1 - t) : t;
            ohid[(size_t)tr * (2 * HID) + dir * HID + j] = hnew;
            if (t == SEQ - 1) olast[j] = hnew;

            gr = ngr; gz = ngz; gn = ngn;
        }
        __syncthreads();   // all 32 leaders' local writes visible

        // ---- push my slice + flag to the 7 peer CTAs
        if (tid < CL - 1) {
            int dst = tid + (tid >= rank);
            unsigned laddr = (unsigned)__cvta_generic_to_shared(&hbuf[p2][rank * HPAD]);
            unsigned raddr;
            asm("mapa.shared::cluster.u32 %0, %1, %2;" : "=r"(raddr) : "r"(laddr), "r"(dst));
            const float4* lp = (const float4*)&hbuf[p2][rank * HPAD];
#pragma unroll
            for (int i = 0; i < 8; i++) {
                float4 v = lp[i];
                asm volatile("st.shared::cluster.v4.f32 [%0], {%1,%2,%3,%4};"
                             :: "r"(raddr + 16u * i), "f"(v.x), "f"(v.y), "f"(v.z), "f"(v.w)
                             : "memory");
            }
            asm volatile("fence.acq_rel.cluster;" ::: "memory");
            unsigned fl = (unsigned)__cvta_generic_to_shared(&flags[rank]);
            unsigned rfl;
            asm("mapa.shared::cluster.u32 %0, %1, %2;" : "=r"(rfl) : "r"(fl), "r"(dst));
            unsigned val = (unsigned)(t + 1);
            asm volatile("st.shared::cluster.u32 [%0], %1;" :: "r"(rfl), "r"(val) : "memory");
        }

        // ---- wait for all 7 peers' slices for this step
        if (tid < CL && tid != rank) {
            volatile unsigned* f = &flags[tid];
            while (*f < (unsigned)(t + 1)) { }
            asm volatile("fence.acq_rel.cluster;" ::: "memory");
        }
        __syncthreads();
    }
}

// ---------------------------------------------------------------------------
extern "C" void kernel_launch(void* const* d_in, const int* in_sizes, int n_in,
                              void* d_out, int out_size)
{
    const int*   utt    = (const int*)  d_in[0];
    const float* hidden = (const float*)d_in[1];
    const float* hidden2= (const float*)d_in[2];
    const float* emb    = (const float*)d_in[3];
    const float* w_ih1  = (const float*)d_in[4];
    const float* w_hh1  = (const float*)d_in[5];
    const float* b_ih1  = (const float*)d_in[6];
    const float* b_hh1  = (const float*)d_in[7];
    const float* w_ih2  = (const float*)d_in[8];
    const float* w_hh2  = (const float*)d_in[9];
    const float* b_ih2  = (const float*)d_in[10];
    const float* b_hh2  = (const float*)d_in[11];
    float* out = (float*)d_out;

    embed_kernel<<<(SEQ * EMBD + 255) / 256, 256>>>(utt, emb, out);
    gi_gemm_kernel<<<dim3(G3 / 64, SEQ / 64, 2), 256>>>(utt, emb, w_ih1, b_ih1, w_ih2, b_ih2);
    gru_kernel<<<2 * CL, 256>>>(w_hh1, b_hh1, w_hh2, b_hh2, hidden, hidden2, out);
}

// round 2
// speedup vs baseline: 1.2501x; 1.2501x over previous
#include <cuda_runtime.h>

#define SEQ  4096
#define EMBD 200
#define HID  256
#define G3   768            // 3*HID gate rows
#define CL   8              // cluster size (CTAs per direction)
#define SLICE 32            // HID / CL  h-outputs per CTA
#define HPAD  36            // padded chunk stride (32 + 4) -> conflict-free banks

// output layout: [embeddings 4096*200][hiddens 4096*512][h1 256][h2 256]
#define OFF_HID (SEQ * EMBD)               // 819200
#define OFF_H1  (OFF_HID + SEQ * 2 * HID)  // 2916352
#define OFF_H2  (OFF_H1 + HID)             // 2916608

typedef unsigned long long u64;

// scratch: precomputed gi = W_ih @ x_t + b_ih for both directions
__device__ float g_gi[2ull * SEQ * G3];

// packed fp32x2 FMA (Blackwell packed-f32 pipe; PTX-only, ptxas never fuses)
#define FMA2(acc, a, b) \
    asm("fma.rn.f32x2 %0, %1, %2, %3;" : "=l"(acc) : "l"(a), "l"(b), "l"(acc))

__device__ __forceinline__ unsigned smem_u32(const void* p) {
    unsigned a;
    asm("{ .reg .u64 t; cvta.to.shared.u64 t, %1; cvt.u32.u64 %0, t; }"
        : "=r"(a) : "l"(p));
    return a;
}

// ---------------------------------------------------------------------------
// Kernel 1: embedding gather -> output section 0
// ---------------------------------------------------------------------------
__global__ void embed_kernel(const int* __restrict__ utt,
                             const float* __restrict__ emb,
                             float* __restrict__ out)
{
    int idx = blockIdx.x * blockDim.x + threadIdx.x;
    if (idx >= SEQ * EMBD) return;
    int t = idx / EMBD;
    int e = idx - t * EMBD;
    out[idx] = emb[(size_t)utt[t] * EMBD + e];
}

// ---------------------------------------------------------------------------
// Kernel 2: gi[d][t][r] = b_ih[r] + sum_k w_ih[r][k] * emb[utt[t]][k]
// tiled fp32 GEMM, 64x64 tiles, k-chunks of 8 (EMBD = 200 = 25*8)
// ---------------------------------------------------------------------------
__global__ void gi_gemm_kernel(const int* __restrict__ utt,
                               const float* __restrict__ emb,
                               const float* __restrict__ wih1,
                               const float* __restrict__ bih1,
                               const float* __restrict__ wih2,
                               const float* __restrict__ bih2)
{
    __shared__ float As[8][64];
    __shared__ float Bs[8][68];   // +4 pad
    __shared__ int   ut[64];

    const int dir = blockIdx.z;
    const float* __restrict__ wih = dir ? wih2 : wih1;
    const float* __restrict__ bih = dir ? bih2 : bih1;
    float* __restrict__ outp = g_gi + (size_t)dir * SEQ * G3;

    const int r0 = blockIdx.x * 64;
    const int t0 = blockIdx.y * 64;
    const int tid = threadIdx.x;

    if (tid < 64) ut[tid] = utt[t0 + tid];
    __syncthreads();

    const int tx = tid & 15;
    const int ty = tid >> 4;
    float c[4][4] = {};

    for (int k0 = 0; k0 < EMBD; k0 += 8) {
#pragma unroll
        for (int l = 0; l < 2; l++) {
            int e  = tid + l * 256;
            int kk = e >> 6;
            int o  = e & 63;
            As[kk][o] = emb[(size_t)ut[o] * EMBD + k0 + kk];
            Bs[kk][o] = wih[(size_t)(r0 + o) * EMBD + k0 + kk];
        }
        __syncthreads();
#pragma unroll
        for (int k = 0; k < 8; k++) {
            float4 a = *(const float4*)&As[k][ty * 4];
            float4 b = *(const float4*)&Bs[k][tx * 4];
            c[0][0] = fmaf(a.x, b.x, c[0][0]); c[0][1] = fmaf(a.x, b.y, c[0][1]);
            c[0][2] = fmaf(a.x, b.z, c[0][2]); c[0][3] = fmaf(a.x, b.w, c[0][3]);
            c[1][0] = fmaf(a.y, b.x, c[1][0]); c[1][1] = fmaf(a.y, b.y, c[1][1]);
            c[1][2] = fmaf(a.y, b.z, c[1][2]); c[1][3] = fmaf(a.y, b.w, c[1][3]);
            c[2][0] = fmaf(a.z, b.x, c[2][0]); c[2][1] = fmaf(a.z, b.y, c[2][1]);
            c[2][2] = fmaf(a.z, b.z, c[2][2]); c[2][3] = fmaf(a.z, b.w, c[2][3]);
            c[3][0] = fmaf(a.w, b.x, c[3][0]); c[3][1] = fmaf(a.w, b.y, c[3][1]);
            c[3][2] = fmaf(a.w, b.z, c[3][2]); c[3][3] = fmaf(a.w, b.w, c[3][3]);
        }
        __syncthreads();
    }

    float4 bb = *(const float4*)&bih[r0 + tx * 4];
#pragma unroll
    for (int i = 0; i < 4; i++) {
        int row = t0 + ty * 4 + i;
        float4 v;
        v.x = c[i][0] + bb.x;
        v.y = c[i][1] + bb.y;
        v.z = c[i][2] + bb.z;
        v.w = c[i][3] + bb.w;
        *(float4*)&outp[(size_t)row * G3 + r0 + tx * 4] = v;
    }
}

// ---------------------------------------------------------------------------
// Kernel 3: sequential bi-GRU recurrence.
// grid = 16 CTAs in clusters of 8: ranks 0-7 = fwd, next 8 = bwd.
// Each thread: 3x32 weights packed as fp32x2 in regs. Per-step handshake:
// parallel 4B st.shared::cluster pushes + one mbarrier.arrive.release.cluster
// per peer CTA; consumers try_wait.parity.acquire.cluster.
// ---------------------------------------------------------------------------
__global__ void __launch_bounds__(256, 1) __cluster_dims__(CL, 1, 1)
gru_kernel(const float* __restrict__ whh1, const float* __restrict__ bhh1,
           const float* __restrict__ whh2, const float* __restrict__ bhh2,
           const float* __restrict__ h01,  const float* __restrict__ h02,
           float* __restrict__ out)
{
    __shared__ float hbuf[2][CL * HPAD];      // double-buffered h (padded chunks)
    __shared__ __align__(8) u64 mbar;         // arrival barrier (7 peers/step)

    const int rank = blockIdx.x & (CL - 1);
    const int dir  = blockIdx.x >> 3;
    const float* __restrict__ whh = dir ? whh2 : whh1;
    const float* __restrict__ bhh = dir ? bhh2 : bhh1;
    const float* __restrict__ h0  = dir ? h02  : h01;
    const float* __restrict__ gi  = g_gi + (size_t)dir * SEQ * G3;
    float* __restrict__ ohid  = out + OFF_HID;
    float* __restrict__ olast = out + (dir ? OFF_H2 : OFF_H1);

    const int tid   = threadIdx.x;
    const int group = tid >> 3;              // 0..31 -> which h-output of my slice
    const int sub   = tid & 7;               // 0..7  -> which 32-wide k-chunk
    const int j     = rank * SLICE + group;  // global h index 0..255
    const int kb    = sub * 32;

    // ---- weights: rows j, 256+j, 512+j; cols kb..kb+31, packed as fp32x2
    u64 wr2[16], wz2[16], wn2[16];
    {
        const ulonglong2* pr = (const ulonglong2*)(whh + (size_t)(          j) * HID + kb);
        const ulonglong2* pz = (const ulonglong2*)(whh + (size_t)(HID     + j) * HID + kb);
        const ulonglong2* pn = (const ulonglong2*)(whh + (size_t)(2 * HID + j) * HID + kb);
#pragma unroll
        for (int i = 0; i < 8; i++) {
            ulonglong2 a = pr[i]; wr2[2*i] = a.x; wr2[2*i+1] = a.y;
            ulonglong2 b = pz[i]; wz2[2*i] = b.x; wz2[2*i+1] = b.y;
            ulonglong2 d = pn[i]; wn2[2*i] = d.x; wn2[2*i+1] = d.y;
        }
    }

    // ---- mbarrier init + local h0
    unsigned mb_l = smem_u32(&mbar);
    if (tid == 0) {
        asm volatile("mbarrier.init.shared.b64 [%0], %1;"
                     :: "r"(mb_l), "r"((unsigned)(CL - 1)) : "memory");
    }
    if (tid < HID) hbuf[0][(tid >> 5) * HPAD + (tid & 31)] = h0[tid];

    // ---- precompute remote addresses (mapa once, outside loop)
    unsigned rd0 = 0, rd1 = 0, rmb = 0;
    if (sub < CL - 1) {
        int dst = sub + (sub >= rank);
        unsigned l0 = smem_u32(&hbuf[0][rank * HPAD + group]);
        unsigned l1 = smem_u32(&hbuf[1][rank * HPAD + group]);
        asm("mapa.shared::cluster.u32 %0, %1, %2;" : "=r"(rd0) : "r"(l0), "r"(dst));
        asm("mapa.shared::cluster.u32 %0, %1, %2;" : "=r"(rd1) : "r"(l1), "r"(dst));
    }
    if (tid < CL - 1) {
        int dst = tid + (tid >= rank);
        asm("mapa.shared::cluster.u32 %0, %1, %2;" : "=r"(rmb) : "r"(mb_l), "r"(dst));
    }

    // ---- per-thread constants: biases + first-step gi (all threads redundant)
    const float bhr = bhh[j], bhz = bhh[HID + j], bhn = bhh[2 * HID + j];
    float gr, gz, gn;
    {
        int tr = dir ? (SEQ - 1) : 0;
        const float* gp = gi + (size_t)tr * G3;
        gr = gp[j]; gz = gp[HID + j]; gn = gp[2 * HID + j];
    }

    __syncthreads();
    // mbar init + hbuf[0] must be cluster-visible before any peer arrives/stores
    asm volatile("barrier.cluster.arrive.aligned;" ::: "memory");
    asm volatile("barrier.cluster.wait.aligned;"   ::: "memory");

    for (int t = 0; t < SEQ; t++) {
        const int p = t & 1;

        // prefetch next step's gi (latency hidden under this step's compute)
        float ngr = 0.f, ngz = 0.f, ngn = 0.f;
        if (t < SEQ - 1) {
            int tr = dir ? (SEQ - 2 - t) : (t + 1);
            const float* gp = gi + (size_t)tr * G3;
            ngr = gp[j]; ngz = gp[HID + j]; ngn = gp[2 * HID + j];
        }

        // ---- partial dots over my 32-wide k-chunk (fp32x2 packed FMA)
        const ulonglong2* hs = (const ulonglong2*)&hbuf[p][sub * HPAD];
        u64 ar2 = 0ull, az2 = 0ull, an2 = 0ull;
#pragma unroll
        for (int i = 0; i < 8; i++) {
            ulonglong2 h2 = hs[i];
            FMA2(ar2, wr2[2*i  ], h2.x); FMA2(az2, wz2[2*i  ], h2.x); FMA2(an2, wn2[2*i  ], h2.x);
            FMA2(ar2, wr2[2*i+1], h2.y); FMA2(az2, wz2[2*i+1], h2.y); FMA2(an2, wn2[2*i+1], h2.y);
        }
        float ar, az, an;
        {
            float lo, hi;
            asm("mov.b64 {%0,%1}, %2;" : "=f"(lo), "=f"(hi) : "l"(ar2)); ar = lo + hi;
            asm("mov.b64 {%0,%1}, %2;" : "=f"(lo), "=f"(hi) : "l"(az2)); az = lo + hi;
            asm("mov.b64 {%0,%1}, %2;" : "=f"(lo), "=f"(hi) : "l"(an2)); an = lo + hi;
        }

        // ---- width-8 butterfly = allreduce: every sub gets the full dot
#pragma unroll
        for (int off = 4; off; off >>= 1) {
            ar += __shfl_xor_sync(0xffffffffu, ar, off, 8);
            az += __shfl_xor_sync(0xffffffffu, az, off, 8);
            an += __shfl_xor_sync(0xffffffffu, an, off, 8);
        }

        // ---- gates (all threads, redundant across subs; full fp32)
        float xr = gr + bhr + ar;
        float xz = gz + bhz + az;
        float r  = __fdividef(1.f, 1.f + __expf(-xr));
        float z  = __fdividef(1.f, 1.f + __expf(-xz));
        float xn = gn + r * (an + bhn);
        float e2 = __expf(-2.f * xn);
        float n  = __fdividef(1.f - e2, 1.f + e2);        // tanh(xn)
        float hp = hbuf[p][rank * HPAD + group];           // h_prev[j]
        float hnew = n + z * (hp - n);                     // (1-z)n + z h

        gr = ngr; gz = ngz; gn = ngn;

        if (sub == 7) hbuf[p ^ 1][rank * HPAD + group] = hnew;   // local slice
        if (sub == 0) {
            int tr = dir ? (SEQ - 1 - t) : t;
            ohid[(size_t)tr * (2 * HID) + dir * HID + j] = hnew;
            if (t == SEQ - 1) olast[j] = hnew;
        }

        if (t < SEQ - 1) {
            // ---- parallel push: 224 threads, one 4B remote store each
            if (sub < CL - 1) {
                unsigned bits = __float_as_uint(hnew);
                unsigned dsta = (p ^ 1) ? rd1 : rd0;
                asm volatile("st.shared::cluster.u32 [%0], %1;"
                             :: "r"(dsta), "r"(bits) : "memory");
            }
            __syncthreads();   // order all this CTA's stores before the release
            if (tid < CL - 1) {
                asm volatile("mbarrier.arrive.release.cluster.shared::cluster.b64 _, [%0];"
                             :: "r"(rmb) : "memory");
            }
            // ---- wait for all 7 peers (acquire @ cluster scope)
            {
                unsigned par = (unsigned)(t & 1);
                unsigned done = 0;
                asm volatile(
                    "{\n\t.reg .pred P;\n\t"
                    "mbarrier.try_wait.parity.acquire.cluster.shared::cta.b64 P, [%1], %2, 0x989680;\n\t"
                    "selp.b32 %0, 1, 0, P;\n\t}"
                    : "=r"(done) : "r"(mb_l), "r"(par) : "memory");
                while (!done) {
                    asm volatile(
                        "{\n\t.reg .pred P;\n\t"
                        "mbarrier.try_wait.parity.acquire.cluster.shared::cta.b64 P, [%1], %2, 0x989680;\n\t"
                        "selp.b32 %0, 1, 0, P;\n\t}"
                        : "=r"(done) : "r"(mb_l), "r"(par) : "memory");
                }
            }
        }
    }

    // no remote ops can be in flight here (last step pushed nothing), but a
    // final cluster barrier is cheap one-time insurance against early exit
    asm volatile("barrier.cluster.arrive.aligned;" ::: "memory");
    asm volatile("barrier.cluster.wait.aligned;"   ::: "memory");
}

// ---------------------------------------------------------------------------
extern "C" void kernel_launch(void* const* d_in, const int* in_sizes, int n_in,
                              void* d_out, int out_size)
{
    const int*   utt     = (const int*)  d_in[0];
    const float* hidden  = (const float*)d_in[1];
    const float* hidden2 = (const float*)d_in[2];
    const float* emb     = (const float*)d_in[3];
    const float* w_ih1   = (const float*)d_in[4];
    const float* w_hh1   = (const float*)d_in[5];
    const float* b_ih1   = (const float*)d_in[6];
    const float* b_hh1   = (const float*)d_in[7];
    const float* w_ih2   = (const float*)d_in[8];
    const float* w_hh2   = (const float*)d_in[9];
    const float* b_ih2   = (const float*)d_in[10];
    const float* b_hh2   = (const float*)d_in[11];
    float* out = (float*)d_out;

    embed_kernel<<<(SEQ * EMBD + 255) / 256, 256>>>(utt, emb, out);
    gi_gemm_kernel<<<dim3(G3 / 64, SEQ / 64, 2), 256>>>(utt, emb, w_ih1, b_ih1, w_ih2, b_ih2);
    gru_kernel<<<2 * CL, 256>>>(w_hh1, b_hh1, w_hh2, b_hh2, hidden, hidden2, out);
}